// round 3
// baseline (speedup 1.0000x reference)
#include <cuda_runtime.h>
#include <math.h>

#define BB 32
#define SS 2048
#define KK 512
#define VV 512
#define HH 256
#define MT (SS*BB)      // 65536 rows (index = s*BB + b)
#define SCH 8           // s-chunks for weighted-sum split
#define SPER (SS/SCH)   // 256

// scratch (static device arrays — no allocation allowed)
__device__ float g_hq2[BB*HH];            // hq + bq + bk, [b][h]
__device__ float g_logit[MT];             // logit[s*BB + b]
__device__ float g_partial[SCH*BB*VV];    // split-S partial weighted sums

// ---------------------------------------------------------------------------
// Kernel 1: hq2[b][h] = q[b]·Wq[h] + bq[h] + bk[h]
// ---------------------------------------------------------------------------
__global__ void hq_kernel(const float* __restrict__ q, const float* __restrict__ Wq,
                          const float* __restrict__ bq, const float* __restrict__ bk) {
    int b = blockIdx.x;
    int h = threadIdx.x;  // 256 threads, one per h
    __shared__ float qs[KK];
    for (int i = threadIdx.x; i < KK; i += blockDim.x) qs[i] = q[b*KK + i];
    __syncthreads();
    const float* w = Wq + (size_t)h * KK;
    float acc = 0.f;
    #pragma unroll 8
    for (int kk = 0; kk < KK; kk++) acc += qs[kk] * w[kk];
    g_hq2[b*HH + h] = acc + bq[h] + bk[h];
}

// ---------------------------------------------------------------------------
// Kernel 2: fused GEMM + tanh + Wo reduction -> logit[row], row = s*BB + b
//   A = k (rows are k[s,b,:], contiguous, M=65536 x K=512)
//   Bmat = Wk^T (K=512 x H=256)
// CTA: 256 threads, tile 64 rows x 256 cols (all of H), BK=16.
// Thread (ty=tid/32, tx=tid%32) owns rows ty*8..+7, cols {tx, tx+32, ..., tx+224}.
// ---------------------------------------------------------------------------
__global__ __launch_bounds__(256, 2) void logit_kernel(
    const float* __restrict__ kmat, const float* __restrict__ Wk,
    const float* __restrict__ Wo,   const float* __restrict__ bo) {
    __shared__ float As[64][16];      // 4 KB
    __shared__ float Bs[16][HH];      // 16 KB  (Bs[kk][h])
    __shared__ float hqs[BB*HH];      // 32 KB
    __shared__ float wos[HH];         // 1 KB

    int tid  = threadIdx.x;
    int base = blockIdx.x * 64;

    for (int i = tid; i < BB*HH; i += 256) hqs[i] = g_hq2[i];
    if (tid < HH) wos[tid] = Wo[tid];

    float acc[8][8];
    #pragma unroll
    for (int i = 0; i < 8; i++)
        #pragma unroll
        for (int j = 0; j < 8; j++) acc[i][j] = 0.f;

    int ty = tid >> 5, tx = tid & 31;
    int arow = tid >> 2, aseg = (tid & 3) * 4;

    for (int k0 = 0; k0 < KK; k0 += 16) {
        // stage gmem loads in registers before the smem handoff
        float4 av  = *(const float4*)(kmat + (size_t)(base + arow)*KK + k0 + aseg);
        float4 bv0 = *(const float4*)(Wk + (size_t)tid*KK + k0 + 0);
        float4 bv1 = *(const float4*)(Wk + (size_t)tid*KK + k0 + 4);
        float4 bv2 = *(const float4*)(Wk + (size_t)tid*KK + k0 + 8);
        float4 bv3 = *(const float4*)(Wk + (size_t)tid*KK + k0 + 12);
        __syncthreads();
        *(float4*)&As[arow][aseg] = av;
        Bs[ 0][tid] = bv0.x; Bs[ 1][tid] = bv0.y; Bs[ 2][tid] = bv0.z; Bs[ 3][tid] = bv0.w;
        Bs[ 4][tid] = bv1.x; Bs[ 5][tid] = bv1.y; Bs[ 6][tid] = bv1.z; Bs[ 7][tid] = bv1.w;
        Bs[ 8][tid] = bv2.x; Bs[ 9][tid] = bv2.y; Bs[10][tid] = bv2.z; Bs[11][tid] = bv2.w;
        Bs[12][tid] = bv3.x; Bs[13][tid] = bv3.y; Bs[14][tid] = bv3.z; Bs[15][tid] = bv3.w;
        __syncthreads();

        #pragma unroll
        for (int kk = 0; kk < 16; kk++) {
            float a[8], bb[8];
            #pragma unroll
            for (int i = 0; i < 8; i++) a[i] = As[ty*8 + i][kk];   // broadcast within warp
            #pragma unroll
            for (int j = 0; j < 8; j++) bb[j] = Bs[kk][j*32 + tx]; // conflict-free
            #pragma unroll
            for (int i = 0; i < 8; i++)
                #pragma unroll
                for (int j = 0; j < 8; j++) acc[i][j] += a[i] * bb[j];
        }
    }

    // epilogue: tanh + Wo-weighted reduce across H, warp-reduce across lanes
    float bo0 = bo[0];
    #pragma unroll
    for (int i = 0; i < 8; i++) {
        int row = base + ty*8 + i;
        int b   = row & (BB - 1);
        float part = 0.f;
        #pragma unroll
        for (int j = 0; j < 8; j++) {
            int h = j*32 + tx;
            part += wos[h] * tanhf(acc[i][j] + hqs[b*HH + h]);
        }
        #pragma unroll
        for (int off = 16; off; off >>= 1)
            part += __shfl_xor_sync(0xffffffffu, part, off);
        if (tx == 0) g_logit[row] = part + bo0;
    }
}

// ---------------------------------------------------------------------------
// Kernel 3: softmax per batch over S; writes final p[b*S+s] into the output.
// ---------------------------------------------------------------------------
__global__ void softmax_kernel(float* __restrict__ p) {
    int b = blockIdx.x, t = threadIdx.x;   // 256 threads
    __shared__ float red[256];
    float m = -3.4e38f;
    for (int s = t; s < SS; s += 256) m = fmaxf(m, g_logit[s*BB + b]);
    red[t] = m; __syncthreads();
    for (int off = 128; off; off >>= 1) {
        if (t < off) red[t] = fmaxf(red[t], red[t + off]);
        __syncthreads();
    }
    m = red[0]; __syncthreads();

    float sum = 0.f;
    for (int s = t; s < SS; s += 256) {
        float e = expf(g_logit[s*BB + b] - m);
        p[b*SS + s] = e;
        sum += e;
    }
    red[t] = sum; __syncthreads();
    for (int off = 128; off; off >>= 1) {
        if (t < off) red[t] += red[t + off];
        __syncthreads();
    }
    float rinv = 1.f / red[0];
    for (int s = t; s < SS; s += 256) p[b*SS + s] *= rinv;
}

// ---------------------------------------------------------------------------
// Kernel 4: partial weighted sum over an s-chunk:
//   g_partial[sc][b][vc] = sum_{s in chunk} p[b][s] * v[s][b][vc]
// ---------------------------------------------------------------------------
__global__ void wsum_kernel(const float* __restrict__ v, const float* __restrict__ p) {
    int b  = blockIdx.x;
    int vc = blockIdx.y * 128 + threadIdx.x;
    int sc = blockIdx.z;
    const float* vp = v + ((size_t)(sc*SPER)*BB + b) * VV + vc;
    const float* pp = p + b*SS + sc*SPER;
    float acc = 0.f;
    #pragma unroll 4
    for (int s = 0; s < SPER; s++)
        acc += pp[s] * vp[(size_t)s * BB * VV];
    g_partial[(sc*BB + b)*VV + vc] = acc;
}

// ---------------------------------------------------------------------------
// Kernel 5: reduce split-S partials -> out[b*V + vc]  (deterministic)
// ---------------------------------------------------------------------------
__global__ void reduce_kernel(float* __restrict__ out) {
    int idx = blockIdx.x * 256 + threadIdx.x;  // 16384 total
    float acc = 0.f;
    #pragma unroll
    for (int c = 0; c < SCH; c++) acc += g_partial[c*BB*VV + idx];
    out[idx] = acc;
}

// ---------------------------------------------------------------------------
extern "C" void kernel_launch(void* const* d_in, const int* in_sizes, int n_in,
                              void* d_out, int out_size) {
    const float* q  = (const float*)d_in[0];
    const float* k  = (const float*)d_in[1];
    const float* v  = (const float*)d_in[2];
    const float* Wk = (const float*)d_in[3];
    const float* bk = (const float*)d_in[4];
    const float* Wq = (const float*)d_in[5];
    const float* bq = (const float*)d_in[6];
    const float* Wo = (const float*)d_in[7];
    const float* bo = (const float*)d_in[8];

    float* out = (float*)d_out;          // [1, B, V] -> B*V floats
    float* p   = out + BB*VV;            // [B, S]    -> B*S floats

    hq_kernel<<<BB, HH>>>(q, Wq, bq, bk);
    logit_kernel<<<MT/64, 256>>>(k, Wk, Wo, bo);
    softmax_kernel<<<BB, 256>>>(p);
    dim3 g4(BB, VV/128, SCH);
    wsum_kernel<<<g4, 128>>>(v, p);
    reduce_kernel<<<BB*VV/256, 256>>>(out);
}

// round 4
// speedup vs baseline: 2.0210x; 2.0210x over previous
#include <cuda_runtime.h>
#include <math.h>
#include <stdint.h>

#define BB 32
#define SS 2048
#define KK 512
#define VV 512
#define HH 256
#define MT (SS*BB)      // 65536 rows (row = s*BB + b)
#define SCH 16          // s-chunks for weighted-sum split
#define SPER (SS/SCH)   // 128

// scratch (static device arrays — no allocation allowed)
__device__ float g_hq2[BB*HH];            // q@Wq + bq + bk, [b][h]
__device__ float g_logit[MT];             // logit[s*BB + b]
__device__ float g_partial[SCH*BB*VV];    // split-S partial weighted sums

__device__ __forceinline__ uint32_t f2tf32(float f) {
    uint32_t r;
    asm("cvt.rna.tf32.f32 %0, %1;" : "=r"(r) : "f"(f));
    return r;
}

#define MMA_TF32(d, a, b)                                                       \
    asm volatile("mma.sync.aligned.m16n8k8.row.col.f32.tf32.tf32.f32 "          \
                 "{%0,%1,%2,%3}, {%4,%5,%6,%7}, {%8,%9}, {%0,%1,%2,%3};"        \
                 : "+f"(d[0]), "+f"(d[1]), "+f"(d[2]), "+f"(d[3])               \
                 : "r"(a[0]), "r"(a[1]), "r"(a[2]), "r"(a[3]),                  \
                   "r"(b[0]), "r"(b[1]))

// ---------------------------------------------------------------------------
// Kernel 1: hq2[b][h] = q[b]·Wq[h] + bq[h] + bk[h]
// ---------------------------------------------------------------------------
__global__ void hq_kernel(const float* __restrict__ q, const float* __restrict__ Wq,
                          const float* __restrict__ bq, const float* __restrict__ bk) {
    int b = blockIdx.x;
    int h = threadIdx.x;  // 256 threads, one per h
    __shared__ float qs[KK];
    for (int i = threadIdx.x; i < KK; i += blockDim.x) qs[i] = q[b*KK + i];
    __syncthreads();
    const float* w = Wq + (size_t)h * KK;
    float acc = 0.f;
    #pragma unroll 8
    for (int kk = 0; kk < KK; kk++) acc += qs[kk] * w[kk];
    g_hq2[b*HH + h] = acc + bq[h] + bk[h];
}

// ---------------------------------------------------------------------------
// Kernel 2: tf32 tensor-core GEMM + tanh + Wo reduction -> logit[row]
//   C[M=65536, N=256] = k[M,512] @ Wk^T;  Wk is [H,K] row-major so the
//   col-major B fragment (B[k][n] = Wk[n][k]) maps directly.
// CTA: 512 threads (16 warps, warp grid 4x4), tile M=128 x N=256, BK=16.
// Warp tile 32x64 -> acc[2][8][4] per thread.
// Smem padded: As stride 20, Bs stride 264 -> conflict-free fragment loads.
// ---------------------------------------------------------------------------
#define AS_STR 20
#define BS_STR 264

__global__ __launch_bounds__(512, 1) void logit_kernel(
    const float* __restrict__ kmat, const float* __restrict__ Wk,
    const float* __restrict__ Wo,   const float* __restrict__ bo) {
    __shared__ uint32_t As[128][AS_STR];   // 10.0 KB (tf32 bits)
    __shared__ uint32_t Bs[16][BS_STR];    // 16.5 KB (tf32 bits)
    __shared__ float wos[HH];              // 1 KB
    __shared__ float red[128][4];          // 2 KB

    const int tid  = threadIdx.x;
    const int lane = tid & 31;
    const int warp = tid >> 5;
    const int wm   = warp >> 2;            // 0..3 (M)
    const int wn   = warp & 3;             // 0..3 (N)
    const int g    = lane >> 2;            // groupID
    const int t    = lane & 3;             // thread-in-group
    const int base = blockIdx.x * 128;

    if (tid < HH) wos[tid] = Wo[tid];

    // staging indices
    const int arow = tid >> 2;             // 0..127
    const int acol = (tid & 3) * 4;        // 0,4,8,12
    const int bh   = tid >> 1;             // 0..255 (h)
    const int bko  = (tid & 1) * 8;        // 0 or 8

    float acc[2][8][4];
    #pragma unroll
    for (int mt = 0; mt < 2; mt++)
        #pragma unroll
        for (int nt = 0; nt < 8; nt++)
            #pragma unroll
            for (int c = 0; c < 4; c++) acc[mt][nt][c] = 0.f;

    const float* apt = kmat + (size_t)(base + arow)*KK + acol;
    const float* bpt = Wk + (size_t)bh*KK + bko;

    for (int k0 = 0; k0 < KK; k0 += 16) {
        // stage gmem loads in registers before the smem handoff
        float4 av  = *(const float4*)(apt + k0);
        float4 bv0 = *(const float4*)(bpt + k0);
        float4 bv1 = *(const float4*)(bpt + k0 + 4);
        __syncthreads();
        uint4 at;
        at.x = f2tf32(av.x); at.y = f2tf32(av.y);
        at.z = f2tf32(av.z); at.w = f2tf32(av.w);
        *(uint4*)&As[arow][acol] = at;                // stride 20 floats = 80B, 16B-aligned
        Bs[bko+0][bh] = f2tf32(bv0.x);
        Bs[bko+1][bh] = f2tf32(bv0.y);
        Bs[bko+2][bh] = f2tf32(bv0.z);
        Bs[bko+3][bh] = f2tf32(bv0.w);
        Bs[bko+4][bh] = f2tf32(bv1.x);
        Bs[bko+5][bh] = f2tf32(bv1.y);
        Bs[bko+6][bh] = f2tf32(bv1.z);
        Bs[bko+7][bh] = f2tf32(bv1.w);
        __syncthreads();

        #pragma unroll
        for (int ks = 0; ks < 2; ks++) {
            const int kk = ks * 8;
            uint32_t afr[2][4];
            #pragma unroll
            for (int mt = 0; mt < 2; mt++) {
                int r = wm*32 + mt*16;
                afr[mt][0] = As[r + g    ][kk + t    ];
                afr[mt][1] = As[r + g + 8][kk + t    ];
                afr[mt][2] = As[r + g    ][kk + t + 4];
                afr[mt][3] = As[r + g + 8][kk + t + 4];
            }
            uint32_t bfr[8][2];
            #pragma unroll
            for (int nt = 0; nt < 8; nt++) {
                int n = wn*64 + nt*8 + g;
                bfr[nt][0] = Bs[kk + t    ][n];
                bfr[nt][1] = Bs[kk + t + 4][n];
            }
            #pragma unroll
            for (int mt = 0; mt < 2; mt++)
                #pragma unroll
                for (int nt = 0; nt < 8; nt++)
                    MMA_TF32(acc[mt][nt], afr[mt], bfr[nt]);
        }
    }

    // epilogue: tanh + Wo-weighted reduce across H
    // C mapping: c0 -> (row g,   col 2t), c1 -> (g, 2t+1),
    //            c2 -> (g+8, 2t), c3 -> (g+8, 2t+1)
    float bo0 = bo[0];
    #pragma unroll
    for (int mt = 0; mt < 2; mt++) {
        #pragma unroll
        for (int rr = 0; rr < 2; rr++) {
            int row_local = wm*32 + mt*16 + rr*8 + g;
            int b = (base + row_local) & (BB - 1);
            const float* hqb = g_hq2 + b*HH;
            float part = 0.f;
            #pragma unroll
            for (int nt = 0; nt < 8; nt++) {
                int h0 = wn*64 + nt*8 + t*2;
                float x0 = acc[mt][nt][rr*2+0] + __ldg(hqb + h0);
                float x1 = acc[mt][nt][rr*2+1] + __ldg(hqb + h0 + 1);
                part += wos[h0] * tanhf(x0) + wos[h0+1] * tanhf(x1);
            }
            // reduce over the 4 lanes sharing this row (t = 0..3)
            part += __shfl_xor_sync(0xffffffffu, part, 1);
            part += __shfl_xor_sync(0xffffffffu, part, 2);
            if (t == 0) red[row_local][wn] = part;
        }
    }
    __syncthreads();
    if (tid < 128)
        g_logit[base + tid] = red[tid][0] + red[tid][1] + red[tid][2] + red[tid][3] + bo0;
}

// ---------------------------------------------------------------------------
// Kernel 3: softmax per batch over S; writes final p[b*S+s] into the output.
// ---------------------------------------------------------------------------
__global__ void softmax_kernel(float* __restrict__ p) {
    int b = blockIdx.x, t = threadIdx.x;   // 256 threads
    __shared__ float red[256];
    float m = -3.4e38f;
    for (int s = t; s < SS; s += 256) m = fmaxf(m, g_logit[s*BB + b]);
    red[t] = m; __syncthreads();
    for (int off = 128; off; off >>= 1) {
        if (t < off) red[t] = fmaxf(red[t], red[t + off]);
        __syncthreads();
    }
    m = red[0]; __syncthreads();

    float sum = 0.f;
    for (int s = t; s < SS; s += 256) {
        float e = expf(g_logit[s*BB + b] - m);
        p[b*SS + s] = e;
        sum += e;
    }
    red[t] = sum; __syncthreads();
    for (int off = 128; off; off >>= 1) {
        if (t < off) red[t] += red[t + off];
        __syncthreads();
    }
    float rinv = 1.f / red[0];
    for (int s = t; s < SS; s += 256) p[b*SS + s] *= rinv;
}

// ---------------------------------------------------------------------------
// Kernel 4: partial weighted sum over an s-chunk (float4, smem-staged p):
//   g_partial[sc][b][vc] = sum_{s in chunk} p[b][s] * v[s][b][vc]
// ---------------------------------------------------------------------------
__global__ void wsum_kernel(const float* __restrict__ v, const float* __restrict__ p) {
    int b  = blockIdx.x;
    int sc = blockIdx.y;
    int vc4 = threadIdx.x;   // 128 threads, one float4 each (covers V=512)
    __shared__ float ps[SPER];
    if (threadIdx.x < SPER) ps[threadIdx.x] = p[b*SS + sc*SPER + threadIdx.x];
    __syncthreads();

    const float4* vp = (const float4*)(v + ((size_t)(sc*SPER)*BB + b) * VV) + vc4;
    const size_t stride4 = (size_t)BB * VV / 4;  // float4 stride over s
    float4 acc = make_float4(0.f, 0.f, 0.f, 0.f);
    #pragma unroll 4
    for (int s = 0; s < SPER; s++) {
        float  w = ps[s];
        float4 tv = vp[(size_t)s * stride4];
        acc.x += w * tv.x; acc.y += w * tv.y;
        acc.z += w * tv.z; acc.w += w * tv.w;
    }
    ((float4*)(g_partial + ((size_t)(sc*BB + b)) * VV))[vc4] = acc;
}

// ---------------------------------------------------------------------------
// Kernel 5: reduce split-S partials -> out[b*V + vc]  (deterministic)
// ---------------------------------------------------------------------------
__global__ void reduce_kernel(float* __restrict__ out) {
    int idx = blockIdx.x * 256 + threadIdx.x;  // 16384 total
    float acc = 0.f;
    #pragma unroll
    for (int c = 0; c < SCH; c++) acc += g_partial[c*BB*VV + idx];
    out[idx] = acc;
}

// ---------------------------------------------------------------------------
extern "C" void kernel_launch(void* const* d_in, const int* in_sizes, int n_in,
                              void* d_out, int out_size) {
    const float* q  = (const float*)d_in[0];
    const float* k  = (const float*)d_in[1];
    const float* v  = (const float*)d_in[2];
    const float* Wk = (const float*)d_in[3];
    const float* bk = (const float*)d_in[4];
    const float* Wq = (const float*)d_in[5];
    const float* bq = (const float*)d_in[6];
    const float* Wo = (const float*)d_in[7];
    const float* bo = (const float*)d_in[8];

    float* out = (float*)d_out;          // [1, B, V] -> B*V floats
    float* p   = out + BB*VV;            // [B, S]    -> B*S floats

    hq_kernel<<<BB, HH>>>(q, Wq, bq, bk);
    logit_kernel<<<MT/128, 512>>>(k, Wk, Wo, bo);
    softmax_kernel<<<BB, 256>>>(p);
    dim3 g4(BB, SCH);
    wsum_kernel<<<g4, 128>>>(v, p);
    reduce_kernel<<<BB*VV/256, 256>>>(out);
}

// round 5
// speedup vs baseline: 2.0890x; 1.0336x over previous
#include <cuda_runtime.h>
#include <math.h>
#include <stdint.h>

#define BB 32
#define SS 2048
#define KK 512
#define VV 512
#define HH 256
#define MT (SS*BB)      // 65536 rows (row = s*BB + b)
#define SCH 32          // s-chunks for weighted-sum split
#define SPER (SS/SCH)   // 64

// scratch (static device arrays — no allocation allowed)
__device__ float g_hq2[BB*HH];            // q@Wq + bq + bk, [b][h]
__device__ float g_logit[MT];             // logit[s*BB + b]
__device__ float g_partial[SCH*BB*VV];    // split-S partial weighted sums

__device__ __forceinline__ uint32_t f2tf32(float f) {
    uint32_t r;
    asm("cvt.rna.tf32.f32 %0, %1;" : "=r"(r) : "f"(f));
    return r;
}

#define MMA_TF32(d, a, b)                                                       \
    asm volatile("mma.sync.aligned.m16n8k8.row.col.f32.tf32.tf32.f32 "          \
                 "{%0,%1,%2,%3}, {%4,%5,%6,%7}, {%8,%9}, {%0,%1,%2,%3};"        \
                 : "+f"(d[0]), "+f"(d[1]), "+f"(d[2]), "+f"(d[3])               \
                 : "r"(a[0]), "r"(a[1]), "r"(a[2]), "r"(a[3]),                  \
                   "r"(b[0]), "r"(b[1]))

// ---------------------------------------------------------------------------
// Kernel 1: hq2[b][h] = q[b]·Wq[h] + bq[h] + bk[h]
// ---------------------------------------------------------------------------
__global__ void hq_kernel(const float* __restrict__ q, const float* __restrict__ Wq,
                          const float* __restrict__ bq, const float* __restrict__ bk) {
    int b = blockIdx.x;
    int h = threadIdx.x;  // 256 threads, one per h
    __shared__ float qs[KK];
    for (int i = threadIdx.x; i < KK; i += blockDim.x) qs[i] = q[b*KK + i];
    __syncthreads();
    const float* w = Wq + (size_t)h * KK;
    float acc = 0.f;
    #pragma unroll 8
    for (int kk = 0; kk < KK; kk++) acc += qs[kk] * w[kk];
    g_hq2[b*HH + h] = acc + bq[h] + bk[h];
}

// ---------------------------------------------------------------------------
// Kernel 2: tf32 tensor-core GEMM + tanh + Wo reduction -> logit[row]
// Software-pipelined: double-buffered smem, register prefetch one tile ahead,
// ONE __syncthreads per k-tile. CTA 512 thr, tile 128x256, BK=16.
// ---------------------------------------------------------------------------
#define AS_STR 20
#define BS_STR 264
#define NK_TILES (KK/16)

__global__ __launch_bounds__(512, 1) void logit_kernel(
    const float* __restrict__ kmat, const float* __restrict__ Wk,
    const float* __restrict__ Wo,   const float* __restrict__ bo) {
    extern __shared__ char smem_raw[];
    uint32_t* AsBuf[2];
    uint32_t* BsBuf[2];
    AsBuf[0] = (uint32_t*)smem_raw;
    AsBuf[1] = AsBuf[0] + 128*AS_STR;
    BsBuf[0] = AsBuf[1] + 128*AS_STR;
    BsBuf[1] = BsBuf[0] + 16*BS_STR;
    float* wos = (float*)(BsBuf[1] + 16*BS_STR);   // [HH]
    float* red = wos + HH;                          // [128][4]

    const int tid  = threadIdx.x;
    const int lane = tid & 31;
    const int warp = tid >> 5;
    const int wm   = warp >> 2;            // 0..3 (M)
    const int wn   = warp & 3;             // 0..3 (N)
    const int g    = lane >> 2;            // groupID
    const int t    = lane & 3;             // thread-in-group
    const int base = blockIdx.x * 128;

    if (tid < HH) wos[tid] = Wo[tid];

    // staging indices
    const int arow = tid >> 2;             // 0..127
    const int acol = (tid & 3) * 4;        // 0,4,8,12
    const int bh   = tid >> 1;             // 0..255 (h)
    const int bko  = (tid & 1) * 8;        // 0 or 8

    float acc[2][8][4];
    #pragma unroll
    for (int mt = 0; mt < 2; mt++)
        #pragma unroll
        for (int nt = 0; nt < 8; nt++)
            #pragma unroll
            for (int c = 0; c < 4; c++) acc[mt][nt][c] = 0.f;

    const float* apt = kmat + (size_t)(base + arow)*KK + acol;
    const float* bpt = Wk + (size_t)bh*KK + bko;

    // ---- prologue: tile 0 -> regs -> smem buf 0 ----
    float4 av  = *(const float4*)(apt);
    float4 bv0 = *(const float4*)(bpt);
    float4 bv1 = *(const float4*)(bpt + 4);
    {
        uint32_t* As = AsBuf[0];
        uint32_t* Bs = BsBuf[0];
        uint4 at;
        at.x = f2tf32(av.x); at.y = f2tf32(av.y);
        at.z = f2tf32(av.z); at.w = f2tf32(av.w);
        *(uint4*)&As[arow*AS_STR + acol] = at;
        Bs[(bko+0)*BS_STR + bh] = f2tf32(bv0.x);
        Bs[(bko+1)*BS_STR + bh] = f2tf32(bv0.y);
        Bs[(bko+2)*BS_STR + bh] = f2tf32(bv0.z);
        Bs[(bko+3)*BS_STR + bh] = f2tf32(bv0.w);
        Bs[(bko+4)*BS_STR + bh] = f2tf32(bv1.x);
        Bs[(bko+5)*BS_STR + bh] = f2tf32(bv1.y);
        Bs[(bko+6)*BS_STR + bh] = f2tf32(bv1.z);
        Bs[(bko+7)*BS_STR + bh] = f2tf32(bv1.w);
    }
    __syncthreads();

    for (int it = 0; it < NK_TILES; it++) {
        // issue gmem loads for tile it+1 BEFORE compute (latency hidden by MMAs)
        if (it + 1 < NK_TILES) {
            int kn = (it + 1) * 16;
            av  = *(const float4*)(apt + kn);
            bv0 = *(const float4*)(bpt + kn);
            bv1 = *(const float4*)(bpt + kn + 4);
        }

        const uint32_t* As = AsBuf[it & 1];
        const uint32_t* Bs = BsBuf[it & 1];
        #pragma unroll
        for (int ks = 0; ks < 2; ks++) {
            const int kk = ks * 8;
            uint32_t afr[2][4];
            #pragma unroll
            for (int mt = 0; mt < 2; mt++) {
                int r = wm*32 + mt*16;
                afr[mt][0] = As[(r + g    )*AS_STR + kk + t    ];
                afr[mt][1] = As[(r + g + 8)*AS_STR + kk + t    ];
                afr[mt][2] = As[(r + g    )*AS_STR + kk + t + 4];
                afr[mt][3] = As[(r + g + 8)*AS_STR + kk + t + 4];
            }
            uint32_t bfr[8][2];
            #pragma unroll
            for (int nt = 0; nt < 8; nt++) {
                int n = wn*64 + nt*8 + g;
                bfr[nt][0] = Bs[(kk + t    )*BS_STR + n];
                bfr[nt][1] = Bs[(kk + t + 4)*BS_STR + n];
            }
            #pragma unroll
            for (int mt = 0; mt < 2; mt++)
                #pragma unroll
                for (int nt = 0; nt < 8; nt++)
                    MMA_TF32(acc[mt][nt], afr[mt], bfr[nt]);
        }

        // store prefetched tile into the other buffer
        if (it + 1 < NK_TILES) {
            uint32_t* Asn = AsBuf[(it + 1) & 1];
            uint32_t* Bsn = BsBuf[(it + 1) & 1];
            uint4 at;
            at.x = f2tf32(av.x); at.y = f2tf32(av.y);
            at.z = f2tf32(av.z); at.w = f2tf32(av.w);
            *(uint4*)&Asn[arow*AS_STR + acol] = at;
            Bsn[(bko+0)*BS_STR + bh] = f2tf32(bv0.x);
            Bsn[(bko+1)*BS_STR + bh] = f2tf32(bv0.y);
            Bsn[(bko+2)*BS_STR + bh] = f2tf32(bv0.z);
            Bsn[(bko+3)*BS_STR + bh] = f2tf32(bv0.w);
            Bsn[(bko+4)*BS_STR + bh] = f2tf32(bv1.x);
            Bsn[(bko+5)*BS_STR + bh] = f2tf32(bv1.y);
            Bsn[(bko+6)*BS_STR + bh] = f2tf32(bv1.z);
            Bsn[(bko+7)*BS_STR + bh] = f2tf32(bv1.w);
        }
        __syncthreads();
    }

    // epilogue: tanh + Wo-weighted reduce across H
    // C mapping: c0 -> (row g, col 2t), c1 -> (g, 2t+1), c2/c3 -> row g+8
    float bo0 = bo[0];
    #pragma unroll
    for (int mt = 0; mt < 2; mt++) {
        #pragma unroll
        for (int rr = 0; rr < 2; rr++) {
            int row_local = wm*32 + mt*16 + rr*8 + g;
            int b = (base + row_local) & (BB - 1);
            const float* hqb = g_hq2 + b*HH;
            float part = 0.f;
            #pragma unroll
            for (int nt = 0; nt < 8; nt++) {
                int h0 = wn*64 + nt*8 + t*2;
                float x0 = acc[mt][nt][rr*2+0] + __ldg(hqb + h0);
                float x1 = acc[mt][nt][rr*2+1] + __ldg(hqb + h0 + 1);
                part += wos[h0] * tanhf(x0) + wos[h0+1] * tanhf(x1);
            }
            part += __shfl_xor_sync(0xffffffffu, part, 1);
            part += __shfl_xor_sync(0xffffffffu, part, 2);
            if (t == 0) red[row_local*4 + wn] = part;
        }
    }
    __syncthreads();
    if (tid < 128)
        g_logit[base + tid] = red[tid*4+0] + red[tid*4+1] + red[tid*4+2] + red[tid*4+3] + bo0;
}

#define LOGIT_SMEM ((2*128*AS_STR + 2*16*BS_STR)*4 + HH*4 + 128*4*4)

// ---------------------------------------------------------------------------
// Kernel 3: softmax per batch over S; writes final p[b*S+s] into the output.
// ---------------------------------------------------------------------------
__global__ void softmax_kernel(float* __restrict__ p) {
    int b = blockIdx.x, t = threadIdx.x;   // 256 threads
    __shared__ float red[256];
    float m = -3.4e38f;
    for (int s = t; s < SS; s += 256) m = fmaxf(m, g_logit[s*BB + b]);
    red[t] = m; __syncthreads();
    for (int off = 128; off; off >>= 1) {
        if (t < off) red[t] = fmaxf(red[t], red[t + off]);
        __syncthreads();
    }
    m = red[0]; __syncthreads();

    float sum = 0.f;
    for (int s = t; s < SS; s += 256) {
        float e = expf(g_logit[s*BB + b] - m);
        p[b*SS + s] = e;
        sum += e;
    }
    red[t] = sum; __syncthreads();
    for (int off = 128; off; off >>= 1) {
        if (t < off) red[t] += red[t + off];
        __syncthreads();
    }
    float rinv = 1.f / red[0];
    for (int s = t; s < SS; s += 256) p[b*SS + s] *= rinv;
}

// ---------------------------------------------------------------------------
// Kernel 4: partial weighted sum over an s-chunk (float4, smem-staged p):
//   g_partial[sc][b][vc] = sum_{s in chunk} p[b][s] * v[s][b][vc]
// ---------------------------------------------------------------------------
__global__ void wsum_kernel(const float* __restrict__ v, const float* __restrict__ p) {
    int b  = blockIdx.x;
    int sc = blockIdx.y;
    int vc4 = threadIdx.x;   // 128 threads, one float4 each (covers V=512)
    __shared__ float ps[SPER];
    if (threadIdx.x < SPER) ps[threadIdx.x] = p[b*SS + sc*SPER + threadIdx.x];
    __syncthreads();

    const float4* vp = (const float4*)(v + ((size_t)(sc*SPER)*BB + b) * VV) + vc4;
    const size_t stride4 = (size_t)BB * VV / 4;  // float4 stride over s
    float4 acc = make_float4(0.f, 0.f, 0.f, 0.f);
    #pragma unroll 8
    for (int s = 0; s < SPER; s++) {
        float  w = ps[s];
        float4 tv = vp[(size_t)s * stride4];
        acc.x += w * tv.x; acc.y += w * tv.y;
        acc.z += w * tv.z; acc.w += w * tv.w;
    }
    ((float4*)(g_partial + ((size_t)(sc*BB + b)) * VV))[vc4] = acc;
}

// ---------------------------------------------------------------------------
// Kernel 5: reduce split-S partials -> out[b*V + vc]  (deterministic)
// ---------------------------------------------------------------------------
__global__ void reduce_kernel(float* __restrict__ out) {
    int idx = blockIdx.x * 256 + threadIdx.x;  // 16384 total
    float acc = 0.f;
    #pragma unroll
    for (int c = 0; c < SCH; c++) acc += g_partial[c*BB*VV + idx];
    out[idx] = acc;
}

// ---------------------------------------------------------------------------
extern "C" void kernel_launch(void* const* d_in, const int* in_sizes, int n_in,
                              void* d_out, int out_size) {
    const float* q  = (const float*)d_in[0];
    const float* k  = (const float*)d_in[1];
    const float* v  = (const float*)d_in[2];
    const float* Wk = (const float*)d_in[3];
    const float* bk = (const float*)d_in[4];
    const float* Wq = (const float*)d_in[5];
    const float* bq = (const float*)d_in[6];
    const float* Wo = (const float*)d_in[7];
    const float* bo = (const float*)d_in[8];

    float* out = (float*)d_out;          // [1, B, V] -> B*V floats
    float* p   = out + BB*VV;            // [B, S]    -> B*S floats

    static int smem_set = 0;
    if (!smem_set) {
        cudaFuncSetAttribute(logit_kernel,
                             cudaFuncAttributeMaxDynamicSharedMemorySize, LOGIT_SMEM);
        smem_set = 1;
    }

    hq_kernel<<<BB, HH>>>(q, Wq, bq, bk);
    logit_kernel<<<MT/128, 512, LOGIT_SMEM>>>(k, Wk, Wo, bo);
    softmax_kernel<<<BB, 256>>>(p);
    dim3 g4(BB, SCH);
    wsum_kernel<<<g4, 128>>>(v, p);
    reduce_kernel<<<BB*VV/256, 256>>>(out);
}